// round 12
// baseline (speedup 1.0000x reference)
#include <cuda_runtime.h>
#include <math.h>

// Shapes: x[2048,64,512], w_qkv[512,1536], out[2048,64,512]
// B=2048 windows, N=64 tokens, CH=512, H=16 heads, D=32, NW=256 mask windows.

#define LOG_SCALE_MAX 4.605170185988091f  // log(100)

// -------- scratch (device globals: allocation-free per harness rules) --------
__device__ float g_q[67108864];        // [b][h][n][d]  fp32, 256MB
__device__ float g_k[67108864];        // [b][h][n][d]
__device__ float g_v[67108864];        // [b][h][n][d]
__device__ float g_o[67108864];        // [b][n][ch]    pre-projection
__device__ float g_bias[16 * 64 * 64]; // [h][i][j] = 16*sigmoid(cpb(...))

// ============================================================================
// K0: CPB relative-position-bias table (one CTA)
// table = relu(rel_table @ w1 + b1) @ w2 ; bias[h,i,j] = 16*sigmoid(table[idx])
// ============================================================================
__global__ void cpb_kernel(const float* __restrict__ rel_table,
                           const float* __restrict__ w1,
                           const float* __restrict__ b1,
                           const float* __restrict__ w2) {
    __shared__ float tab[225][16];
    const int t = threadIdx.x;
    if (t < 225) {
        float t0 = rel_table[t * 2 + 0];
        float t1 = rel_table[t * 2 + 1];
        float acc[16];
#pragma unroll
        for (int h = 0; h < 16; ++h) acc[h] = 0.f;
        for (int j = 0; j < 512; ++j) {
            float hv = fmaf(t0, w1[j], fmaf(t1, w1[512 + j], b1[j]));
            hv = fmaxf(hv, 0.f);
#pragma unroll
            for (int h = 0; h < 16; ++h) acc[h] = fmaf(hv, w2[j * 16 + h], acc[h]);
        }
#pragma unroll
        for (int h = 0; h < 16; ++h) tab[t][h] = acc[h];
    }
    __syncthreads();
    for (int e = t; e < 16 * 64 * 64; e += blockDim.x) {
        int h = e >> 12;
        int i = (e >> 6) & 63;
        int j = e & 63;
        int dh = (i >> 3) - (j >> 3) + 7;   // 0..14
        int dw = (i & 7) - (j & 7) + 7;     // 0..14
        float v = tab[dh * 15 + dw][h];
        g_bias[e] = 16.f / (1.f + expf(-v));
    }
}

// ============================================================================
// K1/K3: fp32 SGEMM, BM=BN=128, BK=8, 256 threads, 8x8 per-thread microtile.
// MODE 0: C = X @ w_qkv + qkv_bias, scattered to g_q/g_k/g_v [b,h,n,d]
// MODE 1: C = g_o @ proj_w + proj_b, written row-major to d_out
//         (g_o is referenced DEVICE-SIDE via the symbol; passing a __device__
//          global's address from host code yields the host shadow address,
//          which HMM happily dereferences as zeros — the round-10 bug.)
// K is fixed at 512 for both.
// ============================================================================
template <int LDB, int MODE>
__global__ void __launch_bounds__(256) gemm128(
    const float* __restrict__ Ain, const float* __restrict__ B,
    const float* __restrict__ bias1, const float* __restrict__ bias2,
    float* __restrict__ outp)
{
    const float* __restrict__ A = (MODE == 1) ? (const float*)g_o : Ain;

    __shared__ float As[8][128];   // transposed: As[k][m]
    __shared__ float Bs[8][128];   // Bs[k][n]

    const int tid  = threadIdx.x;
    const int m0   = blockIdx.y * 128;
    const int n0   = blockIdx.x * 128;
    const int trow = tid >> 4;     // 0..15
    const int tcol = tid & 15;     // 0..15

    float acc[8][8];
#pragma unroll
    for (int i = 0; i < 8; ++i)
#pragma unroll
        for (int j = 0; j < 8; ++j) acc[i][j] = 0.f;

    const int arow = tid >> 1;         // 0..127
    const int acol = (tid & 1) * 4;    // 0 or 4
    const int brow = tid >> 5;         // 0..7
    const int bcol = (tid & 31) * 4;   // 0..124

    for (int k0 = 0; k0 < 512; k0 += 8) {
        float4 av = *(const float4*)&A[(size_t)(m0 + arow) * 512 + k0 + acol];
        float4 bv = *(const float4*)&B[(size_t)(k0 + brow) * LDB + n0 + bcol];
        __syncthreads();
        As[acol + 0][arow] = av.x;
        As[acol + 1][arow] = av.y;
        As[acol + 2][arow] = av.z;
        As[acol + 3][arow] = av.w;
        *(float4*)&Bs[brow][bcol] = bv;
        __syncthreads();
#pragma unroll
        for (int kk = 0; kk < 8; ++kk) {
            float4 a0 = *(const float4*)&As[kk][trow * 8];
            float4 a1 = *(const float4*)&As[kk][trow * 8 + 4];
            float4 b0 = *(const float4*)&Bs[kk][tcol * 8];
            float4 b1 = *(const float4*)&Bs[kk][tcol * 8 + 4];
            float ar[8] = {a0.x, a0.y, a0.z, a0.w, a1.x, a1.y, a1.z, a1.w};
            float br[8] = {b0.x, b0.y, b0.z, b0.w, b1.x, b1.y, b1.z, b1.w};
#pragma unroll
            for (int i = 0; i < 8; ++i)
#pragma unroll
                for (int j = 0; j < 8; ++j)
                    acc[i][j] = fmaf(ar[i], br[j], acc[i][j]);
        }
    }

    const int c0 = n0 + tcol * 8;  // global output column base (multiple of 8)

    if (MODE == 0) {
        // qkv scatter: c = s*512 + h*32 + d ; 8-col chunk stays within one head
        const int s      = c0 >> 9;        // 0=q 1=k 2=v
        const int within = c0 & 511;
        const int h      = within >> 5;
        const int dd     = within & 31;
        float* dst_base  = (s == 0) ? g_q : (s == 1) ? g_k : g_v;
        float bs[8];
#pragma unroll
        for (int j = 0; j < 8; ++j)
            bs[j] = (s == 0) ? bias1[within + j]
                  : (s == 2) ? bias2[within + j] : 0.f;
#pragma unroll
        for (int i = 0; i < 8; ++i) {
            int m = m0 + trow * 8 + i;
            int b = m >> 6, n = m & 63;
            float* dst = dst_base + (((size_t)b * 16 + h) * 64 + n) * 32 + dd;
            float4 o0 = make_float4(acc[i][0] + bs[0], acc[i][1] + bs[1],
                                    acc[i][2] + bs[2], acc[i][3] + bs[3]);
            float4 o1 = make_float4(acc[i][4] + bs[4], acc[i][5] + bs[5],
                                    acc[i][6] + bs[6], acc[i][7] + bs[7]);
            *(float4*)dst       = o0;
            *(float4*)(dst + 4) = o1;
        }
    } else {
        float bs[8];
#pragma unroll
        for (int j = 0; j < 8; ++j) bs[j] = bias1[c0 + j];
#pragma unroll
        for (int i = 0; i < 8; ++i) {
            int m = m0 + trow * 8 + i;
            float* dst = outp + (size_t)m * 512 + c0;
            float4 o0 = make_float4(acc[i][0] + bs[0], acc[i][1] + bs[1],
                                    acc[i][2] + bs[2], acc[i][3] + bs[3]);
            float4 o1 = make_float4(acc[i][4] + bs[4], acc[i][5] + bs[5],
                                    acc[i][6] + bs[6], acc[i][7] + bs[7]);
            *(float4*)dst       = o0;
            *(float4*)(dst + 4) = o1;
        }
    }
}

// ============================================================================
// K2: fused attention per (window b, head h). 128 threads.
// qn = q/||q|| * exp(min(logit_scale,LOG_SCALE_MAX)); kn = k/||k||
// S = qn knT + bias[h] + mask[b%256]; softmax rows; O = P V -> g_o[b,n,h*32+d]
// ============================================================================
__global__ void __launch_bounds__(128) attn_kernel(
    const float* __restrict__ mask,
    const float* __restrict__ logit_scale)
{
    __shared__ float qt[32][64];   // transposed, scale folded in
    __shared__ float kt[32][64];   // transposed
    __shared__ float vv[64][32];
    __shared__ float Ss[64][65];   // padded to 65 to avoid bank conflicts in PV
    __shared__ float inv_sum[64];

    const int t = threadIdx.x;
    const int h = blockIdx.x;
    const int b = blockIdx.y;
    const size_t base = ((size_t)b * 16 + h) * 2048;

    // ---- load V (coalesced) ----
    {
        const float* vg = g_v + base;
        float* vf = (float*)vv;
#pragma unroll
        for (int idx = t; idx < 2048; idx += 128) vf[idx] = vg[idx];
    }

    // ---- load + normalize Q (threads 0..63) / K (threads 64..127), transpose ----
    if (t < 64) {
        const float* qg = g_q + base + t * 32;
        float vals[32];
        float ss = 0.f;
#pragma unroll
        for (int d4 = 0; d4 < 8; ++d4) {
            float4 v4 = *(const float4*)&qg[d4 * 4];
            vals[d4 * 4 + 0] = v4.x; vals[d4 * 4 + 1] = v4.y;
            vals[d4 * 4 + 2] = v4.z; vals[d4 * 4 + 3] = v4.w;
        }
#pragma unroll
        for (int d = 0; d < 32; ++d) ss = fmaf(vals[d], vals[d], ss);
        float scale = expf(fminf(logit_scale[t & 15], LOG_SCALE_MAX)); // any lane; h below
        scale = expf(fminf(logit_scale[h], LOG_SCALE_MAX));
        float inv = scale / sqrtf(ss);
#pragma unroll
        for (int d = 0; d < 32; ++d) qt[d][t] = vals[d] * inv;
    } else {
        const int r = t - 64;
        const float* kg = g_k + base + r * 32;
        float vals[32];
        float ss = 0.f;
#pragma unroll
        for (int d4 = 0; d4 < 8; ++d4) {
            float4 v4 = *(const float4*)&kg[d4 * 4];
            vals[d4 * 4 + 0] = v4.x; vals[d4 * 4 + 1] = v4.y;
            vals[d4 * 4 + 2] = v4.z; vals[d4 * 4 + 3] = v4.w;
        }
#pragma unroll
        for (int d = 0; d < 32; ++d) ss = fmaf(vals[d], vals[d], ss);
        float inv = 1.f / sqrtf(ss);
#pragma unroll
        for (int d = 0; d < 32; ++d) kt[d][r] = vals[d] * inv;
    }
    __syncthreads();

    // ---- S = qn knT (+bias +mask): each thread 4 rows x 8 cols ----
    {
        const int r0 = (t >> 3) * 4;   // 0..60
        const int c0 = (t & 7) * 8;    // 0..56
        float acc[4][8];
#pragma unroll
        for (int i = 0; i < 4; ++i)
#pragma unroll
            for (int j = 0; j < 8; ++j) acc[i][j] = 0.f;
#pragma unroll
        for (int kk = 0; kk < 32; ++kk) {
            float4 a  = *(const float4*)&qt[kk][r0];
            float4 b0 = *(const float4*)&kt[kk][c0];
            float4 b1 = *(const float4*)&kt[kk][c0 + 4];
            float ar[4] = {a.x, a.y, a.z, a.w};
            float br[8] = {b0.x, b0.y, b0.z, b0.w, b1.x, b1.y, b1.z, b1.w};
#pragma unroll
            for (int i = 0; i < 4; ++i)
#pragma unroll
                for (int j = 0; j < 8; ++j)
                    acc[i][j] = fmaf(ar[i], br[j], acc[i][j]);
        }
        const float* mrow = mask + (size_t)(b & 255) * 4096;
        const float* brow = g_bias + h * 4096;
#pragma unroll
        for (int i = 0; i < 4; ++i) {
            int r = r0 + i;
            float4 m0v = *(const float4*)&mrow[r * 64 + c0];
            float4 m1v = *(const float4*)&mrow[r * 64 + c0 + 4];
            float4 b0v = *(const float4*)&brow[r * 64 + c0];
            float4 b1v = *(const float4*)&brow[r * 64 + c0 + 4];
            Ss[r][c0 + 0] = acc[i][0] + m0v.x + b0v.x;
            Ss[r][c0 + 1] = acc[i][1] + m0v.y + b0v.y;
            Ss[r][c0 + 2] = acc[i][2] + m0v.z + b0v.z;
            Ss[r][c0 + 3] = acc[i][3] + m0v.w + b0v.w;
            Ss[r][c0 + 4] = acc[i][4] + m1v.x + b1v.x;
            Ss[r][c0 + 5] = acc[i][5] + m1v.y + b1v.y;
            Ss[r][c0 + 6] = acc[i][6] + m1v.z + b1v.z;
            Ss[r][c0 + 7] = acc[i][7] + m1v.w + b1v.w;
        }
    }
    __syncthreads();

    // ---- softmax: 2 threads per row (adjacent lanes, shfl_xor combine) ----
    {
        const int row = t >> 1;
        const int off = (t & 1) * 32;
        float mx = -1e30f;
#pragma unroll
        for (int j = 0; j < 32; ++j) mx = fmaxf(mx, Ss[row][off + j]);
        mx = fmaxf(mx, __shfl_xor_sync(0xffffffffu, mx, 1));
        float sm = 0.f;
#pragma unroll
        for (int j = 0; j < 32; ++j) {
            float e = expf(Ss[row][off + j] - mx);
            Ss[row][off + j] = e;
            sm += e;
        }
        sm += __shfl_xor_sync(0xffffffffu, sm, 1);
        if ((t & 1) == 0) inv_sum[row] = 1.f / sm;
    }
    __syncthreads();

    // ---- O = P V: each thread 4 rows x 4 cols ----
    {
        const int r0 = (t >> 3) * 4;   // 0..60
        const int c0 = (t & 7) * 4;    // 0..28
        float acc[4][4];
#pragma unroll
        for (int i = 0; i < 4; ++i)
#pragma unroll
            for (int j = 0; j < 4; ++j) acc[i][j] = 0.f;
#pragma unroll
        for (int kk = 0; kk < 64; ++kk) {
            float4 bv = *(const float4*)&vv[kk][c0];
#pragma unroll
            for (int i = 0; i < 4; ++i) {
                float a = Ss[r0 + i][kk];
                acc[i][0] = fmaf(a, bv.x, acc[i][0]);
                acc[i][1] = fmaf(a, bv.y, acc[i][1]);
                acc[i][2] = fmaf(a, bv.z, acc[i][2]);
                acc[i][3] = fmaf(a, bv.w, acc[i][3]);
            }
        }
#pragma unroll
        for (int i = 0; i < 4; ++i) {
            int r = r0 + i;
            float is = inv_sum[r];
            float4 o4 = make_float4(acc[i][0] * is, acc[i][1] * is,
                                    acc[i][2] * is, acc[i][3] * is);
            *(float4*)&g_o[((size_t)b * 64 + r) * 512 + h * 32 + c0] = o4;
        }
    }
}

// ============================================================================
// launch
// ============================================================================
extern "C" void kernel_launch(void* const* d_in, const int* in_sizes, int n_in,
                              void* d_out, int out_size) {
    const float* x           = (const float*)d_in[0];   // [2048,64,512]
    const float* mask        = (const float*)d_in[1];   // [256,64,64]
    const float* rel_table   = (const float*)d_in[2];   // [1,15,15,2]
    const float* w_qkv       = (const float*)d_in[3];   // [512,1536]
    const float* q_bias      = (const float*)d_in[4];   // [512]
    const float* v_bias      = (const float*)d_in[5];   // [512]
    const float* logit_scale = (const float*)d_in[6];   // [16]
    const float* cpb_w1      = (const float*)d_in[7];   // [2,512]
    const float* cpb_b1      = (const float*)d_in[8];   // [512]
    const float* cpb_w2      = (const float*)d_in[9];   // [512,16]
    const float* proj_w      = (const float*)d_in[10];  // [512,512]
    const float* proj_b      = (const float*)d_in[11];  // [512]
    float* out = (float*)d_out;                          // [2048,64,512]

    // K0: CPB bias table (tiny)
    cpb_kernel<<<1, 256>>>(rel_table, cpb_w1, cpb_b1, cpb_w2);

    // K1: QKV GEMM + bias + scatter to [b,h,n,d]
    gemm128<1536, 0><<<dim3(12, 1024), 256>>>(x, w_qkv, q_bias, v_bias, nullptr);

    // K2: fused window attention per (head, window)
    attn_kernel<<<dim3(16, 2048), 128>>>(mask, logit_scale);

    // K3: output projection + bias (reads g_o device-side; Ain ignored)
    gemm128<512, 1><<<dim3(4, 1024), 256>>>(nullptr, proj_w, proj_b, nullptr, out);
}

// round 15
// speedup vs baseline: 2.1823x; 2.1823x over previous
#include <cuda_runtime.h>
#include <cuda_bf16.h>
#include <math.h>
#include <stdint.h>

// B=2048 windows, N=64 tokens, CH=512, H=16 heads, D=32, NW=256 mask windows.
#define LOG_SCALE_MAX 4.605170185988091f  // log(100)

// -------- scratch (device globals; referenced DEVICE-SIDE only) --------
__device__ float g_q[67108864];            // [b][h][n][d] fp32
__device__ float g_k[67108864];
__device__ float g_v[67108864];
__device__ float g_bias[16 * 64 * 64];     // [h][i][j]
__device__ __nv_bfloat16 g_xhi[67108864];  // x split hi  [m][k]
__device__ __nv_bfloat16 g_xlo[67108864];  // x split lo
__device__ __nv_bfloat16 g_ohi[67108864];  // attention out split hi [m][ch]
__device__ __nv_bfloat16 g_olo[67108864];
__device__ __nv_bfloat16 g_wqh[1536 * 512];// w_qkv^T split hi  [n][k]
__device__ __nv_bfloat16 g_wql[1536 * 512];
__device__ __nv_bfloat16 g_wph[512 * 512]; // proj_w^T split hi [n][k]
__device__ __nv_bfloat16 g_wpl[512 * 512];

// ============================ helpers =======================================
__device__ __forceinline__ uint32_t smem_u32(const void* p) {
    uint32_t a;
    asm("{ .reg .u64 t; cvta.to.shared.u64 t, %1; cvt.u32.u64 %0, t; }"
        : "=r"(a) : "l"(p));
    return a;
}
__device__ __forceinline__ void bsplit(float v, __nv_bfloat16& h, __nv_bfloat16& l) {
    h = __float2bfloat16(v);
    l = __float2bfloat16(v - __bfloat162float(h));
}
__device__ __forceinline__ void cp16(uint32_t dst, const void* src) {
    asm volatile("cp.async.cg.shared.global [%0], [%1], 16;"
                 :: "r"(dst), "l"(src) : "memory");
}
__device__ __forceinline__ void cp_commit() {
    asm volatile("cp.async.commit_group;" ::: "memory");
}
__device__ __forceinline__ void cp_wait0() {
    asm volatile("cp.async.wait_group 0;" ::: "memory");
}
__device__ __forceinline__ void ldsm4(uint32_t& r0, uint32_t& r1, uint32_t& r2,
                                      uint32_t& r3, uint32_t addr) {
    asm volatile("ldmatrix.sync.aligned.m8n8.x4.shared.b16 {%0,%1,%2,%3}, [%4];"
                 : "=r"(r0), "=r"(r1), "=r"(r2), "=r"(r3) : "r"(addr));
}
__device__ __forceinline__ void mma_bf16(float* d, const uint32_t* a, const uint32_t* b) {
    asm volatile(
        "mma.sync.aligned.m16n8k16.row.col.f32.bf16.bf16.f32 "
        "{%0,%1,%2,%3}, {%4,%5,%6,%7}, {%8,%9}, {%0,%1,%2,%3};"
        : "+f"(d[0]), "+f"(d[1]), "+f"(d[2]), "+f"(d[3])
        : "r"(a[0]), "r"(a[1]), "r"(a[2]), "r"(a[3]), "r"(b[0]), "r"(b[1]));
}

// ============================================================================
// K0: CPB relative-position-bias table (one CTA)
// ============================================================================
__global__ void cpb_kernel(const float* __restrict__ rel_table,
                           const float* __restrict__ w1,
                           const float* __restrict__ b1,
                           const float* __restrict__ w2) {
    __shared__ float tab[225][16];
    const int t = threadIdx.x;
    if (t < 225) {
        float t0 = rel_table[t * 2 + 0];
        float t1 = rel_table[t * 2 + 1];
        float acc[16];
#pragma unroll
        for (int h = 0; h < 16; ++h) acc[h] = 0.f;
        for (int j = 0; j < 512; ++j) {
            float hv = fmaf(t0, w1[j], fmaf(t1, w1[512 + j], b1[j]));
            hv = fmaxf(hv, 0.f);
#pragma unroll
            for (int h = 0; h < 16; ++h) acc[h] = fmaf(hv, w2[j * 16 + h], acc[h]);
        }
#pragma unroll
        for (int h = 0; h < 16; ++h) tab[t][h] = acc[h];
    }
    __syncthreads();
    for (int e = t; e < 16 * 64 * 64; e += blockDim.x) {
        int h = e >> 12;
        int i = (e >> 6) & 63;
        int j = e & 63;
        int dh = (i >> 3) - (j >> 3) + 7;
        int dw = (i & 7) - (j & 7) + 7;
        float v = tab[dh * 15 + dw][h];
        g_bias[e] = 16.f / (1.f + expf(-v));
    }
}

// ============================================================================
// Conversion pre-passes: fp32 -> (bf16 hi, bf16 lo)
// ============================================================================
__global__ void convert_x(const float* __restrict__ src) {
    size_t i = (size_t)blockIdx.x * 256 + threadIdx.x;  // per float4
    float4 v = ((const float4*)src)[i];
    __nv_bfloat16 h0, h1, h2, h3, l0, l1, l2, l3;
    bsplit(v.x, h0, l0); bsplit(v.y, h1, l1);
    bsplit(v.z, h2, l2); bsplit(v.w, h3, l3);
    __nv_bfloat162 H0; H0.x = h0; H0.y = h1;
    __nv_bfloat162 H1; H1.x = h2; H1.y = h3;
    __nv_bfloat162 L0; L0.x = l0; L0.y = l1;
    __nv_bfloat162 L1; L1.x = l2; L1.y = l3;
    ((__nv_bfloat162*)g_xhi)[i * 2 + 0] = H0;
    ((__nv_bfloat162*)g_xhi)[i * 2 + 1] = H1;
    ((__nv_bfloat162*)g_xlo)[i * 2 + 0] = L0;
    ((__nv_bfloat162*)g_xlo)[i * 2 + 1] = L1;
}

// w is [512, N] row-major; output [N][512] K-major splits
template <int WHICH>  // 0: w_qkv (N=1536) ; 1: proj (N=512)
__global__ void convert_wT(const float* __restrict__ w) {
    const int N = (WHICH == 0) ? 1536 : 512;
    int idx = blockIdx.x * 256 + threadIdx.x;
    if (idx >= N * 512) return;
    int n = idx >> 9, k = idx & 511;
    float v = w[(size_t)k * N + n];
    __nv_bfloat16 h, l;
    bsplit(v, h, l);
    if (WHICH == 0) { g_wqh[idx] = h; g_wql[idx] = l; }
    else            { g_wph[idx] = h; g_wpl[idx] = l; }
}

// ============================================================================
// Tensor-core GEMM via mma.sync (baseline PTX; no tcgen05 on this toolchain).
// C[M,N] = A @ B^T, K=512, bf16 hi/lo 3-MMA split, fp32 accumulate.
// CTA tile 128x128, BK=32, 8 warps (warp tile 64x32), cp.async double buffer.
// MODE 0: A = x splits, B = w_qkv^T splits -> scatter g_q/g_k/g_v (+qkv bias)
// MODE 1: A = attn-out splits, B = proj_w^T splits -> d_out (+proj_b)
// ============================================================================
template <int MODE>
__global__ void __launch_bounds__(256) gemm_mma(const float* __restrict__ b1,
                                                const float* __restrict__ b2,
                                                float* __restrict__ outp) {
    extern __shared__ char smem[];
    const uint32_t sb = smem_u32(smem);
    const int tid = threadIdx.x, lane = tid & 31, wid = tid >> 5;
    const int m0 = blockIdx.y * 128, n0 = blockIdx.x * 128;
    const int wm = wid >> 2, wn = wid & 3;   // warp grid 2(M) x 4(N)

    const __nv_bfloat16* __restrict__ Ahi = (MODE == 0) ? g_xhi : g_ohi;
    const __nv_bfloat16* __restrict__ Alo = (MODE == 0) ? g_xlo : g_olo;
    const __nv_bfloat16* __restrict__ Bhi = (MODE == 0) ? g_wqh : g_wph;
    const __nv_bfloat16* __restrict__ Blo = (MODE == 0) ? g_wql : g_wpl;

    // stage layout (bytes): AH @0, AL @10240, BH @20480, BL @30720 ; 80B/row
    const int ST = 40960;  // per-stage bytes; double buffered = 81920

    float acc[4][4][4];
#pragma unroll
    for (int i = 0; i < 4; ++i)
#pragma unroll
        for (int j = 0; j < 4; ++j)
#pragma unroll
            for (int f = 0; f < 4; ++f) acc[i][j][f] = 0.f;

    auto stage = [&](int ch, int buf) {
        const int k0 = ch * 32;
        const uint32_t s0 = sb + buf * ST;
#pragma unroll
        for (int it = 0; it < 2; ++it) {
            int idx = tid + it * 256;          // 0..511
            int r = idx >> 2;                  // 0..127
            int kc = (idx & 3) * 8;            // 0,8,16,24
            uint32_t d = (uint32_t)(r * 80 + kc * 2);
            size_t ga = (size_t)(m0 + r) * 512 + k0 + kc;
            size_t gb = (size_t)(n0 + r) * 512 + k0 + kc;
            cp16(s0 + d,         Ahi + ga);
            cp16(s0 + 10240 + d, Alo + ga);
            cp16(s0 + 20480 + d, Bhi + gb);
            cp16(s0 + 30720 + d, Blo + gb);
        }
        cp_commit();
    };

    // ldmatrix per-thread base offsets (bytes, within a stage)
    const uint32_t a_base = (uint32_t)((wm * 64 + (lane & 15)) * 80 + (lane >> 4) * 16);
    const uint32_t b_base = (uint32_t)((wn * 32 + (lane & 7) + ((lane >> 4) << 3)) * 80 +
                                       ((lane >> 3) & 1) * 16);

    stage(0, 0);

    for (int ch = 0; ch < 16; ++ch) {
        cp_wait0();
        __syncthreads();
        if (ch < 15) stage(ch + 1, (ch + 1) & 1);

        const uint32_t s0 = sb + (ch & 1) * ST;
#pragma unroll
        for (int ks = 0; ks < 2; ++ks) {
            uint32_t ah[4][4], al[4][4], bh[4][2], bl[4][2];
#pragma unroll
            for (int mt = 0; mt < 4; ++mt) {
                uint32_t addr = s0 + a_base + mt * 1280 + ks * 32;
                ldsm4(ah[mt][0], ah[mt][1], ah[mt][2], ah[mt][3], addr);
                ldsm4(al[mt][0], al[mt][1], al[mt][2], al[mt][3], addr + 10240);
            }
#pragma unroll
            for (int p = 0; p < 2; ++p) {
                uint32_t addr = s0 + 20480 + b_base + p * 1280 + ks * 32;
                uint32_t r0, r1, r2, r3;
                ldsm4(r0, r1, r2, r3, addr);
                bh[2 * p][0] = r0; bh[2 * p][1] = r1;
                bh[2 * p + 1][0] = r2; bh[2 * p + 1][1] = r3;
                ldsm4(r0, r1, r2, r3, addr + 10240);
                bl[2 * p][0] = r0; bl[2 * p][1] = r1;
                bl[2 * p + 1][0] = r2; bl[2 * p + 1][1] = r3;
            }
            // three product passes: hi*hi, hi*lo, lo*hi (spaced for acc deps)
#pragma unroll
            for (int mt = 0; mt < 4; ++mt)
#pragma unroll
                for (int nt = 0; nt < 4; ++nt)
                    mma_bf16(acc[mt][nt], ah[mt], bh[nt]);
#pragma unroll
            for (int mt = 0; mt < 4; ++mt)
#pragma unroll
                for (int nt = 0; nt < 4; ++nt)
                    mma_bf16(acc[mt][nt], ah[mt], bl[nt]);
#pragma unroll
            for (int mt = 0; mt < 4; ++mt)
#pragma unroll
                for (int nt = 0; nt < 4; ++nt)
                    mma_bf16(acc[mt][nt], al[mt], bh[nt]);
        }
        __syncthreads();
    }

    // ---- epilogue: fragment rows (g, g+8), cols (2c, 2c+1) ----
#pragma unroll
    for (int mt = 0; mt < 4; ++mt) {
        int row = m0 + wm * 64 + mt * 16 + (lane >> 2);
#pragma unroll
        for (int nt = 0; nt < 4; ++nt) {
            int col = n0 + wn * 32 + nt * 8 + 2 * (lane & 3);
            if (MODE == 0) {
                int s = col >> 9, within = col & 511;
                int hh = within >> 5, dd = within & 31;
                float bv0 = (s == 0) ? b1[within]     : (s == 2) ? b2[within]     : 0.f;
                float bv1 = (s == 0) ? b1[within + 1] : (s == 2) ? b2[within + 1] : 0.f;
                float* base = (s == 0) ? g_q : (s == 1) ? g_k : g_v;
                int b = row >> 6, n = row & 63;
                float* dst = base + (((size_t)b * 16 + hh) * 64 + n) * 32 + dd;
                *(float2*)dst = make_float2(acc[mt][nt][0] + bv0, acc[mt][nt][1] + bv1);
                *(float2*)(dst + 8 * 32) =
                    make_float2(acc[mt][nt][2] + bv0, acc[mt][nt][3] + bv1);
            } else {
                float bv0 = b1[col], bv1 = b1[col + 1];
                float* dst = outp + (size_t)row * 512 + col;
                *(float2*)dst = make_float2(acc[mt][nt][0] + bv0, acc[mt][nt][1] + bv1);
                *(float2*)(dst + 8 * 512) =
                    make_float2(acc[mt][nt][2] + bv0, acc[mt][nt][3] + bv1);
            }
        }
    }
}

// ============================================================================
// K2: fused attention per (window b, head h). 128 threads.
// Writes output as bf16 hi/lo splits for the tensor-core projection GEMM.
// ============================================================================
__global__ void __launch_bounds__(128) attn_kernel(
    const float* __restrict__ mask,
    const float* __restrict__ logit_scale)
{
    __shared__ float qt[32][64];
    __shared__ float kt[32][64];
    __shared__ float vv[64][32];
    __shared__ float Ss[64][65];
    __shared__ float inv_sum[64];

    const int t = threadIdx.x;
    const int h = blockIdx.x;
    const int b = blockIdx.y;
    const size_t base = ((size_t)b * 16 + h) * 2048;

    {
        const float* vg = g_v + base;
        float* vf = (float*)vv;
#pragma unroll
        for (int idx = t; idx < 2048; idx += 128) vf[idx] = vg[idx];
    }

    if (t < 64) {
        const float* qg = g_q + base + t * 32;
        float vals[32];
        float ss = 0.f;
#pragma unroll
        for (int d4 = 0; d4 < 8; ++d4) {
            float4 v4 = *(const float4*)&qg[d4 * 4];
            vals[d4 * 4 + 0] = v4.x; vals[d4 * 4 + 1] = v4.y;
            vals[d4 * 4 + 2] = v4.z; vals[d4 * 4 + 3] = v4.w;
        }
#pragma unroll
        for (int d = 0; d < 32; ++d) ss = fmaf(vals[d], vals[d], ss);
        float scale = expf(fminf(logit_scale[h], LOG_SCALE_MAX));
        float inv = scale / sqrtf(ss);
#pragma unroll
        for (int d = 0; d < 32; ++d) qt[d][t] = vals[d] * inv;
    } else {
        const int r = t - 64;
        const float* kg = g_k + base + r * 32;
        float vals[32];
        float ss = 0.f;
#pragma unroll
        for (int d4 = 0; d4 < 8; ++d4) {
            float4 v4 = *(const float4*)&kg[d4 * 4];
            vals[d4 * 4 + 0] = v4.x; vals[d4 * 4 + 1] = v4.y;
            vals[d4 * 4 + 2] = v4.z; vals[d4 * 4 + 3] = v4.w;
        }
#pragma unroll
        for (int d = 0; d < 32; ++d) ss = fmaf(vals[d], vals[d], ss);
        float inv = 1.f / sqrtf(ss);
#pragma unroll
        for (int d = 0; d < 32; ++d) kt[d][r] = vals[d] * inv;
    }
    __syncthreads();

    {
        const int r0 = (t >> 3) * 4;
        const int c0 = (t & 7) * 8;
        float acc[4][8];
#pragma unroll
        for (int i = 0; i < 4; ++i)
#pragma unroll
            for (int j = 0; j < 8; ++j) acc[i][j] = 0.f;
#pragma unroll
        for (int kk = 0; kk < 32; ++kk) {
            float4 a  = *(const float4*)&qt[kk][r0];
            float4 b0 = *(const float4*)&kt[kk][c0];
            float4 b1 = *(const float4*)&kt[kk][c0 + 4];
            float ar[4] = {a.x, a.y, a.z, a.w};
            float br[8] = {b0.x, b0.y, b0.z, b0.w, b1.x, b1.y, b1.z, b1.w};
#pragma unroll
            for (int i = 0; i < 4; ++i)
#pragma unroll
                for (int j = 0; j < 8; ++j)
                    acc[i][j] = fmaf(ar[i], br[j], acc[i][j]);
        }
        const float* mrow = mask + (size_t)(b & 255) * 4096;
        const float* brow = g_bias + h * 4096;
#pragma unroll
        for (int i = 0; i < 4; ++i) {
            int r = r0 + i;
            float4 m0v = *(const float4*)&mrow[r * 64 + c0];
            float4 m1v = *(const float4*)&mrow[r * 64 + c0 + 4];
            float4 b0v = *(const float4*)&brow[r * 64 + c0];
            float4 b1v = *(const float4*)&brow[r * 64 + c0 + 4];
            Ss[r][c0 + 0] = acc[i][0] + m0v.x + b0v.x;
            Ss[r][c0 + 1] = acc[i][1] + m0v.y + b0v.y;
            Ss[r][c0 + 2] = acc[i][2] + m0v.z + b0v.z;
            Ss[r][c0 + 3] = acc[i][3] + m0v.w + b0v.w;
            Ss[r][c0 + 4] = acc[i][4] + m1v.x + b1v.x;
            Ss[r][c0 + 5] = acc[i][5] + m1v.y + b1v.y;
            Ss[r][c0 + 6] = acc[i][6] + m1v.z + b1v.z;
            Ss[r][c0 + 7] = acc[i][7] + m1v.w + b1v.w;
        }
    }
    __syncthreads();

    {
        const int row = t >> 1;
        const int off = (t & 1) * 32;
        float mx = -1e30f;
#pragma unroll
        for (int j = 0; j < 32; ++j) mx = fmaxf(mx, Ss[row][off + j]);
        mx = fmaxf(mx, __shfl_xor_sync(0xffffffffu, mx, 1));
        float sm = 0.f;
#pragma unroll
        for (int j = 0; j < 32; ++j) {
            float e = expf(Ss[row][off + j] - mx);
            Ss[row][off + j] = e;
            sm += e;
        }
        sm += __shfl_xor_sync(0xffffffffu, sm, 1);
        if ((t & 1) == 0) inv_sum[row] = 1.f / sm;
    }
    __syncthreads();

    {
        const int r0 = (t >> 3) * 4;
        const int c0 = (t & 7) * 4;
        float acc[4][4];
#pragma unroll
        for (int i = 0; i < 4; ++i)
#pragma unroll
            for (int j = 0; j < 4; ++j) acc[i][j] = 0.f;
#pragma unroll
        for (int kk = 0; kk < 64; ++kk) {
            float4 bv = *(const float4*)&vv[kk][c0];
#pragma unroll
            for (int i = 0; i < 4; ++i) {
                float a = Ss[r0 + i][kk];
                acc[i][0] = fmaf(a, bv.x, acc[i][0]);
                acc[i][1] = fmaf(a, bv.y, acc[i][1]);
                acc[i][2] = fmaf(a, bv.z, acc[i][2]);
                acc[i][3] = fmaf(a, bv.w, acc[i][3]);
            }
        }
#pragma unroll
        for (int i = 0; i < 4; ++i) {
            int r = r0 + i;
            float is = inv_sum[r];
            float o0 = acc[i][0] * is, o1 = acc[i][1] * is;
            float o2 = acc[i][2] * is, o3 = acc[i][3] * is;
            __nv_bfloat16 h0, h1, h2, h3, l0, l1, l2, l3;
            bsplit(o0, h0, l0); bsplit(o1, h1, l1);
            bsplit(o2, h2, l2); bsplit(o3, h3, l3);
            size_t off = ((size_t)b * 64 + r) * 512 + h * 32 + c0;
            __nv_bfloat162 H0; H0.x = h0; H0.y = h1;
            __nv_bfloat162 H1; H1.x = h2; H1.y = h3;
            __nv_bfloat162 L0; L0.x = l0; L0.y = l1;
            __nv_bfloat162 L1; L1.x = l2; L1.y = l3;
            *(__nv_bfloat162*)&g_ohi[off]     = H0;
            *(__nv_bfloat162*)&g_ohi[off + 2] = H1;
            *(__nv_bfloat162*)&g_olo[off]     = L0;
            *(__nv_bfloat162*)&g_olo[off + 2] = L1;
        }
    }
}

// ============================================================================
// launch
// ============================================================================
extern "C" void kernel_launch(void* const* d_in, const int* in_sizes, int n_in,
                              void* d_out, int out_size) {
    const float* x           = (const float*)d_in[0];
    const float* mask        = (const float*)d_in[1];
    const float* rel_table   = (const float*)d_in[2];
    const float* w_qkv       = (const float*)d_in[3];
    const float* q_bias      = (const float*)d_in[4];
    const float* v_bias      = (const float*)d_in[5];
    const float* logit_scale = (const float*)d_in[6];
    const float* cpb_w1      = (const float*)d_in[7];
    const float* cpb_b1      = (const float*)d_in[8];
    const float* cpb_w2      = (const float*)d_in[9];
    const float* proj_w      = (const float*)d_in[10];
    const float* proj_b      = (const float*)d_in[11];
    float* out = (float*)d_out;

    const int SMEM_GEMM = 81920;  // 2 stages x 40960
    cudaFuncSetAttribute(gemm_mma<0>, cudaFuncAttributeMaxDynamicSharedMemorySize, SMEM_GEMM);
    cudaFuncSetAttribute(gemm_mma<1>, cudaFuncAttributeMaxDynamicSharedMemorySize, SMEM_GEMM);

    // tiny pre-passes
    cpb_kernel<<<1, 256>>>(rel_table, cpb_w1, cpb_b1, cpb_w2);
    convert_x<<<65536, 256>>>(x);
    convert_wT<0><<<3072, 256>>>(w_qkv);
    convert_wT<1><<<1024, 256>>>(proj_w);

    // K1: QKV GEMM (tensor cores via mma.sync) -> g_q/g_k/g_v fp32
    gemm_mma<0><<<dim3(12, 1024), 256, SMEM_GEMM>>>(q_bias, v_bias, nullptr);

    // K2: fused window attention -> g_ohi/g_olo bf16 splits
    attn_kernel<<<dim3(16, 2048), 128>>>(mask, logit_scale);

    // K3: output projection (tensor cores) -> out
    gemm_mma<1><<<dim3(4, 1024), 256, SMEM_GEMM>>>(proj_b, nullptr, out);
}

// round 16
// speedup vs baseline: 2.4298x; 1.1134x over previous
#include <cuda_runtime.h>
#include <cuda_bf16.h>
#include <cuda_fp16.h>
#include <math.h>
#include <stdint.h>

// B=2048 windows, N=64 tokens, CH=512, H=16 heads, D=32, NW=256 mask windows.
#define LOG_SCALE_MAX 4.605170185988091f  // log(100)

// -------- scratch (device globals; referenced DEVICE-SIDE only) --------
__device__ float g_q[67108864];            // [b][h][n][d] fp32
__device__ float g_k[67108864];
__device__ float g_v[67108864];
__device__ float g_bias[16 * 64 * 64];     // [h][i][j]
__device__ __nv_bfloat16 g_xhi[67108864];  // x split hi  [m][k]  (QK path)
__device__ __nv_bfloat16 g_xlo[67108864];  // x split lo
__device__ __half        g_xf16[67108864]; // x fp16            (V path)
__device__ __half        g_of16[67108864]; // attention out fp16 [m][ch]
__device__ __nv_bfloat16 g_wqh[1024 * 512];// w_qkv^T QK-cols split hi [n][k]
__device__ __nv_bfloat16 g_wql[1024 * 512];
__device__ __half        g_wv16[512 * 512];// w_qkv^T V-cols fp16 [n][k]
__device__ __half        g_wp16[512 * 512];// proj_w^T fp16 [n][k]

// ============================ helpers =======================================
__device__ __forceinline__ uint32_t smem_u32(const void* p) {
    uint32_t a;
    asm("{ .reg .u64 t; cvta.to.shared.u64 t, %1; cvt.u32.u64 %0, t; }"
        : "=r"(a) : "l"(p));
    return a;
}
__device__ __forceinline__ void bsplit(float v, __nv_bfloat16& h, __nv_bfloat16& l) {
    h = __float2bfloat16(v);
    l = __float2bfloat16(v - __bfloat162float(h));
}
__device__ __forceinline__ void cp16(uint32_t dst, const void* src) {
    asm volatile("cp.async.cg.shared.global [%0], [%1], 16;"
                 :: "r"(dst), "l"(src) : "memory");
}
__device__ __forceinline__ void cp_commit() {
    asm volatile("cp.async.commit_group;" ::: "memory");
}
__device__ __forceinline__ void cp_wait0() {
    asm volatile("cp.async.wait_group 0;" ::: "memory");
}
__device__ __forceinline__ void cp_wait1() {
    asm volatile("cp.async.wait_group 1;" ::: "memory");
}
__device__ __forceinline__ void cp_wait2() {
    asm volatile("cp.async.wait_group 2;" ::: "memory");
}
__device__ __forceinline__ void ldsm4(uint32_t& r0, uint32_t& r1, uint32_t& r2,
                                      uint32_t& r3, uint32_t addr) {
    asm volatile("ldmatrix.sync.aligned.m8n8.x4.shared.b16 {%0,%1,%2,%3}, [%4];"
                 : "=r"(r0), "=r"(r1), "=r"(r2), "=r"(r3) : "r"(addr));
}
__device__ __forceinline__ void mma_bf16(float* d, const uint32_t* a, const uint32_t* b) {
    asm volatile(
        "mma.sync.aligned.m16n8k16.row.col.f32.bf16.bf16.f32 "
        "{%0,%1,%2,%3}, {%4,%5,%6,%7}, {%8,%9}, {%0,%1,%2,%3};"
        : "+f"(d[0]), "+f"(d[1]), "+f"(d[2]), "+f"(d[3])
        : "r"(a[0]), "r"(a[1]), "r"(a[2]), "r"(a[3]), "r"(b[0]), "r"(b[1]));
}
__device__ __forceinline__ void mma_f16(float* d, const uint32_t* a, const uint32_t* b) {
    asm volatile(
        "mma.sync.aligned.m16n8k16.row.col.f32.f16.f16.f32 "
        "{%0,%1,%2,%3}, {%4,%5,%6,%7}, {%8,%9}, {%0,%1,%2,%3};"
        : "+f"(d[0]), "+f"(d[1]), "+f"(d[2]), "+f"(d[3])
        : "r"(a[0]), "r"(a[1]), "r"(a[2]), "r"(a[3]), "r"(b[0]), "r"(b[1]));
}

// ============================================================================
// K0: CPB relative-position-bias table (one CTA)
// ============================================================================
__global__ void cpb_kernel(const float* __restrict__ rel_table,
                           const float* __restrict__ w1,
                           const float* __restrict__ b1,
                           const float* __restrict__ w2) {
    __shared__ float tab[225][16];
    const int t = threadIdx.x;
    if (t < 225) {
        float t0 = rel_table[t * 2 + 0];
        float t1 = rel_table[t * 2 + 1];
        float acc[16];
#pragma unroll
        for (int h = 0; h < 16; ++h) acc[h] = 0.f;
        for (int j = 0; j < 512; ++j) {
            float hv = fmaf(t0, w1[j], fmaf(t1, w1[512 + j], b1[j]));
            hv = fmaxf(hv, 0.f);
#pragma unroll
            for (int h = 0; h < 16; ++h) acc[h] = fmaf(hv, w2[j * 16 + h], acc[h]);
        }
#pragma unroll
        for (int h = 0; h < 16; ++h) tab[t][h] = acc[h];
    }
    __syncthreads();
    for (int e = t; e < 16 * 64 * 64; e += blockDim.x) {
        int h = e >> 12;
        int i = (e >> 6) & 63;
        int j = e & 63;
        int dh = (i >> 3) - (j >> 3) + 7;
        int dw = (i & 7) - (j & 7) + 7;
        float v = tab[dh * 15 + dw][h];
        g_bias[e] = 16.f / (1.f + expf(-v));
    }
}

// ============================================================================
// Conversion pre-passes
// ============================================================================
__global__ void convert_x(const float* __restrict__ src) {
    size_t i = (size_t)blockIdx.x * 256 + threadIdx.x;  // per float4
    float4 v = ((const float4*)src)[i];
    __nv_bfloat16 h0, h1, h2, h3, l0, l1, l2, l3;
    bsplit(v.x, h0, l0); bsplit(v.y, h1, l1);
    bsplit(v.z, h2, l2); bsplit(v.w, h3, l3);
    __nv_bfloat162 H0; H0.x = h0; H0.y = h1;
    __nv_bfloat162 H1; H1.x = h2; H1.y = h3;
    __nv_bfloat162 L0; L0.x = l0; L0.y = l1;
    __nv_bfloat162 L1; L1.x = l2; L1.y = l3;
    ((__nv_bfloat162*)g_xhi)[i * 2 + 0] = H0;
    ((__nv_bfloat162*)g_xhi)[i * 2 + 1] = H1;
    ((__nv_bfloat162*)g_xlo)[i * 2 + 0] = L0;
    ((__nv_bfloat162*)g_xlo)[i * 2 + 1] = L1;
    ((__half2*)g_xf16)[i * 2 + 0] = __floats2half2_rn(v.x, v.y);
    ((__half2*)g_xf16)[i * 2 + 1] = __floats2half2_rn(v.z, v.w);
}

// w_qkv is [512, 1536]; QK cols -> bf16 splits [n][k]; V cols -> fp16 [n-1024][k]
__global__ void convert_wqkv(const float* __restrict__ w) {
    int idx = blockIdx.x * 256 + threadIdx.x;
    if (idx >= 1536 * 512) return;
    int n = idx >> 9, k = idx & 511;
    float v = w[(size_t)k * 1536 + n];
    if (n < 1024) {
        __nv_bfloat16 h, l;
        bsplit(v, h, l);
        g_wqh[n * 512 + k] = h;
        g_wql[n * 512 + k] = l;
    } else {
        g_wv16[(n - 1024) * 512 + k] = __float2half_rn(v);
    }
}
__global__ void convert_proj(const float* __restrict__ w) {
    int idx = blockIdx.x * 256 + threadIdx.x;
    if (idx >= 512 * 512) return;
    int n = idx >> 9, k = idx & 511;
    g_wp16[idx] = __float2half_rn(w[(size_t)k * 512 + n]);
}

// ============================================================================
// Tensor-core GEMM via mma.sync. C[M,N] = A @ B^T, K=512, fp32 accum.
// CTA tile 128x128, BK=32, 8 warps (warp tile 64x32), multi-stage cp.async.
// MODE 0: QK cols. bf16 hi/lo 3-pass. A=x splits, B=w_qkv^T[0:1024) splits.
//         epilogue -> g_q (+q_bias) / g_k. Grid x = 8.
// MODE 1: V cols. fp16 1-pass. A=g_xf16, B=g_wv16 -> g_v (+v_bias). Grid x = 4.
// MODE 2: proj.   fp16 1-pass. A=g_of16, B=g_wp16 -> d_out (+proj_b). Grid x = 4.
// ============================================================================
template <int MODE>
__global__ void __launch_bounds__(256) gemm_mma(const float* __restrict__ b1,
                                                float* __restrict__ outp) {
    constexpr int ST   = (MODE == 0) ? 40960 : 20480;   // bytes per stage
    constexpr int S    = (MODE == 0) ? 3 : 4;           // pipeline stages
    constexpr int BOFF = (MODE == 0) ? 20480 : 10240;   // B-hi tile offset

    extern __shared__ char smem[];
    const uint32_t sb = smem_u32(smem);
    const int tid = threadIdx.x, lane = tid & 31, wid = tid >> 5;
    const int m0 = blockIdx.y * 128, n0 = blockIdx.x * 128;
    const int wm = wid >> 2, wn = wid & 3;   // warp grid 2(M) x 4(N)

    const uint16_t* __restrict__ Ahi =
        (MODE == 0) ? (const uint16_t*)g_xhi
                    : (MODE == 1) ? (const uint16_t*)g_xf16 : (const uint16_t*)g_of16;
    const uint16_t* __restrict__ Alo = (MODE == 0) ? (const uint16_t*)g_xlo : nullptr;
    const uint16_t* __restrict__ Bhi =
        (MODE == 0) ? (const uint16_t*)g_wqh
                    : (MODE == 1) ? (const uint16_t*)g_wv16 : (const uint16_t*)g_wp16;
    const uint16_t* __restrict__ Blo = (MODE == 0) ? (const uint16_t*)g_wql : nullptr;

    float acc[4][4][4];
#pragma unroll
    for (int i = 0; i < 4; ++i)
#pragma unroll
        for (int j = 0; j < 4; ++j)
#pragma unroll
            for (int f = 0; f < 4; ++f) acc[i][j][f] = 0.f;

    auto stage = [&](int ch, int buf) {
        const int k0 = ch * 32;
        const uint32_t s0 = sb + buf * ST;
#pragma unroll
        for (int it = 0; it < 2; ++it) {
            int idx = tid + it * 256;          // 0..511
            int r = idx >> 2;                  // 0..127
            int kc = (idx & 3) * 8;            // 0,8,16,24
            uint32_t d = (uint32_t)(r * 80 + kc * 2);
            size_t ga = (size_t)(m0 + r) * 512 + k0 + kc;
            size_t gb = (size_t)(n0 + r) * 512 + k0 + kc;
            cp16(s0 + d, Ahi + ga);
            if (MODE == 0) {
                cp16(s0 + 10240 + d, Alo + ga);
                cp16(s0 + 20480 + d, Bhi + gb);
                cp16(s0 + 30720 + d, Blo + gb);
            } else {
                cp16(s0 + 10240 + d, Bhi + gb);
            }
        }
        cp_commit();
    };

    // ldmatrix per-thread base offsets (bytes, within a stage)
    const uint32_t a_base = (uint32_t)((wm * 64 + (lane & 15)) * 80 + (lane >> 4) * 16);
    const uint32_t b_base = (uint32_t)((wn * 32 + (lane & 7) + ((lane >> 4) << 3)) * 80 +
                                       ((lane >> 3) & 1) * 16);

    stage(0, 0);
    stage(1, 1);
    if (S == 4) stage(2, 2);

    for (int ch = 0; ch < 16; ++ch) {
        // wait until chunk ch's group is complete (tail drains fully)
        const int rem = 15 - ch;
        if (S == 3) {
            if (rem >= 1) cp_wait1(); else cp_wait0();
        } else {
            if (rem >= 2) cp_wait2(); else if (rem == 1) cp_wait1(); else cp_wait0();
        }
        __syncthreads();
        if (ch + S - 1 < 16) stage(ch + S - 1, (ch + S - 1) % S);

        const uint32_t s0 = sb + (ch % S) * ST;
#pragma unroll
        for (int ks = 0; ks < 2; ++ks) {
            uint32_t ah[4][4], bh[4][2];
#pragma unroll
            for (int mt = 0; mt < 4; ++mt) {
                uint32_t addr = s0 + a_base + mt * 1280 + ks * 32;
                ldsm4(ah[mt][0], ah[mt][1], ah[mt][2], ah[mt][3], addr);
            }
#pragma unroll
            for (int p = 0; p < 2; ++p) {
                uint32_t addr = s0 + BOFF + b_base + p * 1280 + ks * 32;
                uint32_t r0, r1, r2, r3;
                ldsm4(r0, r1, r2, r3, addr);
                bh[2 * p][0] = r0; bh[2 * p][1] = r1;
                bh[2 * p + 1][0] = r2; bh[2 * p + 1][1] = r3;
            }
            if (MODE == 0) {
                uint32_t al[4][4], bl[4][2];
#pragma unroll
                for (int mt = 0; mt < 4; ++mt) {
                    uint32_t addr = s0 + 10240 + a_base + mt * 1280 + ks * 32;
                    ldsm4(al[mt][0], al[mt][1], al[mt][2], al[mt][3], addr);
                }
#pragma unroll
                for (int p = 0; p < 2; ++p) {
                    uint32_t addr = s0 + 30720 + b_base + p * 1280 + ks * 32;
                    uint32_t r0, r1, r2, r3;
                    ldsm4(r0, r1, r2, r3, addr);
                    bl[2 * p][0] = r0; bl[2 * p][1] = r1;
                    bl[2 * p + 1][0] = r2; bl[2 * p + 1][1] = r3;
                }
#pragma unroll
                for (int mt = 0; mt < 4; ++mt)
#pragma unroll
                    for (int nt = 0; nt < 4; ++nt)
                        mma_bf16(acc[mt][nt], ah[mt], bh[nt]);
#pragma unroll
                for (int mt = 0; mt < 4; ++mt)
#pragma unroll
                    for (int nt = 0; nt < 4; ++nt)
                        mma_bf16(acc[mt][nt], ah[mt], bl[nt]);
#pragma unroll
                for (int mt = 0; mt < 4; ++mt)
#pragma unroll
                    for (int nt = 0; nt < 4; ++nt)
                        mma_bf16(acc[mt][nt], al[mt], bh[nt]);
            } else {
#pragma unroll
                for (int mt = 0; mt < 4; ++mt)
#pragma unroll
                    for (int nt = 0; nt < 4; ++nt)
                        mma_f16(acc[mt][nt], ah[mt], bh[nt]);
            }
        }
        __syncthreads();
    }

    // ---- epilogue: fragment rows (g, g+8), cols (2c, 2c+1) ----
#pragma unroll
    for (int mt = 0; mt < 4; ++mt) {
        int row = m0 + wm * 64 + mt * 16 + (lane >> 2);
#pragma unroll
        for (int nt = 0; nt < 4; ++nt) {
            int col = n0 + wn * 32 + nt * 8 + 2 * (lane & 3);
            if (MODE == 2) {
                float bv0 = b1[col], bv1 = b1[col + 1];
                float* dst = outp + (size_t)row * 512 + col;
                *(float2*)dst = make_float2(acc[mt][nt][0] + bv0, acc[mt][nt][1] + bv1);
                *(float2*)(dst + 8 * 512) =
                    make_float2(acc[mt][nt][2] + bv0, acc[mt][nt][3] + bv1);
            } else {
                int within, s;
                float* base;
                if (MODE == 0) {
                    s = col >> 9;            // 0=q, 1=k
                    within = col & 511;
                    base = (s == 0) ? g_q : g_k;
                } else {
                    s = 2;
                    within = col;
                    base = g_v;
                }
                float bv0 = 0.f, bv1 = 0.f;
                if (MODE == 1) { bv0 = b1[within]; bv1 = b1[within + 1]; }
                else if (s == 0) { bv0 = b1[within]; bv1 = b1[within + 1]; }
                int hh = within >> 5, dd = within & 31;
                int b = row >> 6, n = row & 63;
                float* dst = base + (((size_t)b * 16 + hh) * 64 + n) * 32 + dd;
                *(float2*)dst = make_float2(acc[mt][nt][0] + bv0, acc[mt][nt][1] + bv1);
                *(float2*)(dst + 8 * 32) =
                    make_float2(acc[mt][nt][2] + bv0, acc[mt][nt][3] + bv1);
            }
        }
    }
}

// ============================================================================
// K2: fused attention per (window b, head h). 128 threads. Output -> fp16.
// ============================================================================
__global__ void __launch_bounds__(128) attn_kernel(
    const float* __restrict__ mask,
    const float* __restrict__ logit_scale)
{
    __shared__ float qt[32][64];
    __shared__ float kt[32][64];
    __shared__ float vv[64][32];
    __shared__ float Ss[64][65];
    __shared__ float inv_sum[64];

    const int t = threadIdx.x;
    const int h = blockIdx.x;
    const int b = blockIdx.y;
    const size_t base = ((size_t)b * 16 + h) * 2048;

    {
        const float* vg = g_v + base;
        float* vf = (float*)vv;
#pragma unroll
        for (int idx = t; idx < 2048; idx += 128) vf[idx] = vg[idx];
    }

    if (t < 64) {
        const float* qg = g_q + base + t * 32;
        float vals[32];
        float ss = 0.f;
#pragma unroll
        for (int d4 = 0; d4 < 8; ++d4) {
            float4 v4 = *(const float4*)&qg[d4 * 4];
            vals[d4 * 4 + 0] = v4.x; vals[d4 * 4 + 1] = v4.y;
            vals[d4 * 4 + 2] = v4.z; vals[d4 * 4 + 3] = v4.w;
        }
#pragma unroll
        for (int d = 0; d < 32; ++d) ss = fmaf(vals[d], vals[d], ss);
        float scale = expf(fminf(logit_scale[h], LOG_SCALE_MAX));
        float inv = scale / sqrtf(ss);
#pragma unroll
        for (int d = 0; d < 32; ++d) qt[d][t] = vals[d] * inv;
    } else {
        const int r = t - 64;
        const float* kg = g_k + base + r * 32;
        float vals[32];
        float ss = 0.f;
#pragma unroll
        for (int d4 = 0; d4 < 8; ++d4) {
            float4 v4 = *(const float4*)&kg[d4 * 4];
            vals[d4 * 4 + 0] = v4.x; vals[d4 * 4 + 1] = v4.y;
            vals[d4 * 4 + 2] = v4.z; vals[d4 * 4 + 3] = v4.w;
        }
#pragma unroll
        for (int d = 0; d < 32; ++d) ss = fmaf(vals[d], vals[d], ss);
        float inv = 1.f / sqrtf(ss);
#pragma unroll
        for (int d = 0; d < 32; ++d) kt[d][r] = vals[d] * inv;
    }
    __syncthreads();

    {
        const int r0 = (t >> 3) * 4;
        const int c0 = (t & 7) * 8;
        float acc[4][8];
#pragma unroll
        for (int i = 0; i < 4; ++i)
#pragma unroll
            for (int j = 0; j < 8; ++j) acc[i][j] = 0.f;
#pragma unroll
        for (int kk = 0; kk < 32; ++kk) {
            float4 a  = *(const float4*)&qt[kk][r0];
            float4 b0 = *(const float4*)&kt[kk][c0];
            float4 b1 = *(const float4*)&kt[kk][c0 + 4];
            float ar[4] = {a.x, a.y, a.z, a.w};
            float br[8] = {b0.x, b0.y, b0.z, b0.w, b1.x, b1.y, b1.z, b1.w};
#pragma unroll
            for (int i = 0; i < 4; ++i)
#pragma unroll
                for (int j = 0; j < 8; ++j)
                    acc[i][j] = fmaf(ar[i], br[j], acc[i][j]);
        }
        const float* mrow = mask + (size_t)(b & 255) * 4096;
        const float* brow = g_bias + h * 4096;
#pragma unroll
        for (int i = 0; i < 4; ++i) {
            int r = r0 + i;
            float4 m0v = *(const float4*)&mrow[r * 64 + c0];
            float4 m1v = *(const float4*)&mrow[r * 64 + c0 + 4];
            float4 b0v = *(const float4*)&brow[r * 64 + c0];
            float4 b1v = *(const float4*)&brow[r * 64 + c0 + 4];
            Ss[r][c0 + 0] = acc[i][0] + m0v.x + b0v.x;
            Ss[r][c0 + 1] = acc[i][1] + m0v.y + b0v.y;
            Ss[r][c0 + 2] = acc[i][2] + m0v.z + b0v.z;
            Ss[r][c0 + 3] = acc[i][3] + m0v.w + b0v.w;
            Ss[r][c0 + 4] = acc[i][4] + m1v.x + b1v.x;
            Ss[r][c0 + 5] = acc[i][5] + m1v.y + b1v.y;
            Ss[r][c0 + 6] = acc[i][6] + m1v.z + b1v.z;
            Ss[r][c0 + 7] = acc[i][7] + m1v.w + b1v.w;
        }
    }
    __syncthreads();

    {
        const int row = t >> 1;
        const int off = (t & 1) * 32;
        float mx = -1e30f;
#pragma unroll
        for (int j = 0; j < 32; ++j) mx = fmaxf(mx, Ss[row][off + j]);
        mx = fmaxf(mx, __shfl_xor_sync(0xffffffffu, mx, 1));
        float sm = 0.f;
#pragma unroll
        for (int j = 0; j < 32; ++j) {
            float e = expf(Ss[row][off + j] - mx);
            Ss[row][off + j] = e;
            sm += e;
        }
        sm += __shfl_xor_sync(0xffffffffu, sm, 1);
        if ((t & 1) == 0) inv_sum[row] = 1.f / sm;
    }
    __syncthreads();

    {
        const int r0 = (t >> 3) * 4;
        const int c0 = (t & 7) * 4;
        float acc[4][4];
#pragma unroll
        for (int i = 0; i < 4; ++i)
#pragma unroll
            for (int j = 0; j < 4; ++j) acc[i][j] = 0.f;
#pragma unroll
        for (int kk = 0; kk < 64; ++kk) {
            float4 bv = *(const float4*)&vv[kk][c0];
#pragma unroll
            for (int i = 0; i < 4; ++i) {
                float a = Ss[r0 + i][kk];
                acc[i][0] = fmaf(a, bv.x, acc[i][0]);
                acc[i][1] = fmaf(a, bv.y, acc[i][1]);
                acc[i][2] = fmaf(a, bv.z, acc[i][2]);
                acc[i][3] = fmaf(a, bv.w, acc[i][3]);
            }
        }
#pragma unroll
        for (int i = 0; i < 4; ++i) {
            int r = r0 + i;
            float is = inv_sum[r];
            size_t off = ((size_t)b * 64 + r) * 512 + h * 32 + c0;
            *(__half2*)&g_of16[off]     = __floats2half2_rn(acc[i][0] * is, acc[i][1] * is);
            *(__half2*)&g_of16[off + 2] = __floats2half2_rn(acc[i][2] * is, acc[i][3] * is);
        }
    }
}

// ============================================================================
// launch
// ============================================================================
extern "C" void kernel_launch(void* const* d_in, const int* in_sizes, int n_in,
                              void* d_out, int out_size) {
    const float* x           = (const float*)d_in[0];
    const float* mask        = (const float*)d_in[1];
    const float* rel_table   = (const float*)d_in[2];
    const float* w_qkv       = (const float*)d_in[3];
    const float* q_bias      = (const float*)d_in[4];
    const float* v_bias      = (const float*)d_in[5];
    const float* logit_scale = (const float*)d_in[6];
    const float* cpb_w1      = (const float*)d_in[7];
    const float* cpb_b1      = (const float*)d_in[8];
    const float* cpb_w2      = (const float*)d_in[9];
    const float* proj_w      = (const float*)d_in[10];
    const float* proj_b      = (const float*)d_in[11];
    float* out = (float*)d_out;

    const int SMEM0 = 3 * 40960;   // 122880
    const int SMEM1 = 4 * 20480;   // 81920
    cudaFuncSetAttribute(gemm_mma<0>, cudaFuncAttributeMaxDynamicSharedMemorySize, SMEM0);
    cudaFuncSetAttribute(gemm_mma<1>, cudaFuncAttributeMaxDynamicSharedMemorySize, SMEM1);
    cudaFuncSetAttribute(gemm_mma<2>, cudaFuncAttributeMaxDynamicSharedMemorySize, SMEM1);

    // tiny pre-passes
    cpb_kernel<<<1, 256>>>(rel_table, cpb_w1, cpb_b1, cpb_w2);
    convert_x<<<65536, 256>>>(x);
    convert_wqkv<<<3072, 256>>>(w_qkv);
    convert_proj<<<1024, 256>>>(proj_w);

    // K1a: Q,K columns (bf16 3-pass split) -> g_q/g_k
    gemm_mma<0><<<dim3(8, 1024), 256, SMEM0>>>(q_bias, nullptr);
    // K1b: V columns (fp16 1-pass) -> g_v
    gemm_mma<1><<<dim3(4, 1024), 256, SMEM1>>>(v_bias, nullptr);

    // K2: fused window attention -> g_of16
    attn_kernel<<<dim3(16, 2048), 128>>>(mask, logit_scale);

    // K3: output projection (fp16 1-pass) -> out
    gemm_mma<2><<<dim3(4, 1024), 256, SMEM1>>>(proj_b, out);
}

// round 17
// speedup vs baseline: 2.8052x; 1.1545x over previous
#include <cuda_runtime.h>
#include <cuda_bf16.h>
#include <cuda_fp16.h>
#include <math.h>
#include <stdint.h>

// B=2048 windows, N=64 tokens, CH=512, H=16 heads, D=32, NW=256 mask windows.
#define LOG_SCALE_MAX 4.605170185988091f  // log(100)

// -------- scratch (device globals; referenced DEVICE-SIDE only) --------
__device__ float g_q[67108864];            // [b][h][n][d] fp32
__device__ float g_k[67108864];
__device__ float g_v[67108864];
__device__ float g_bias[16 * 64 * 64];     // [h][i][j]
__device__ __nv_bfloat16 g_xhi[67108864];  // x split hi  [m][k]  (QK path)
__device__ __nv_bfloat16 g_xlo[67108864];  // x split lo
__device__ __half        g_xf16[67108864]; // x fp16            (V path)
__device__ __half        g_of16[67108864]; // attention out fp16 [m][ch]
__device__ __nv_bfloat16 g_wqh[1024 * 512];// w_qkv^T QK-cols split hi [n][k]
__device__ __nv_bfloat16 g_wql[1024 * 512];
__device__ __half        g_wv16[512 * 512];// w_qkv^T V-cols fp16 [n][k]
__device__ __half        g_wp16[512 * 512];// proj_w^T fp16 [n][k]

// ============================ helpers =======================================
__device__ __forceinline__ uint32_t smem_u32(const void* p) {
    uint32_t a;
    asm("{ .reg .u64 t; cvta.to.shared.u64 t, %1; cvt.u32.u64 %0, t; }"
        : "=r"(a) : "l"(p));
    return a;
}
__device__ __forceinline__ void bsplit(float v, __nv_bfloat16& h, __nv_bfloat16& l) {
    h = __float2bfloat16(v);
    l = __float2bfloat16(v - __bfloat162float(h));
}
__device__ __forceinline__ uint32_t pack_bf(__nv_bfloat16 lo, __nv_bfloat16 hi) {
    unsigned short a = *(unsigned short*)&lo;
    unsigned short b = *(unsigned short*)&hi;
    return ((uint32_t)b << 16) | a;
}
__device__ __forceinline__ uint32_t pack_h2(float lo, float hi) {
    __half2 h = __floats2half2_rn(lo, hi);
    return *(uint32_t*)&h;
}
__device__ __forceinline__ void cp16(uint32_t dst, const void* src) {
    asm volatile("cp.async.cg.shared.global [%0], [%1], 16;"
                 :: "r"(dst), "l"(src) : "memory");
}
__device__ __forceinline__ void cp_commit() {
    asm volatile("cp.async.commit_group;" ::: "memory");
}
__device__ __forceinline__ void cp_wait0() {
    asm volatile("cp.async.wait_group 0;" ::: "memory");
}
__device__ __forceinline__ void cp_wait1() {
    asm volatile("cp.async.wait_group 1;" ::: "memory");
}
__device__ __forceinline__ void cp_wait2() {
    asm volatile("cp.async.wait_group 2;" ::: "memory");
}
__device__ __forceinline__ void ldsm4(uint32_t& r0, uint32_t& r1, uint32_t& r2,
                                      uint32_t& r3, uint32_t addr) {
    asm volatile("ldmatrix.sync.aligned.m8n8.x4.shared.b16 {%0,%1,%2,%3}, [%4];"
                 : "=r"(r0), "=r"(r1), "=r"(r2), "=r"(r3) : "r"(addr));
}
__device__ __forceinline__ void mma_bf16(float* d, const uint32_t* a, const uint32_t* b) {
    asm volatile(
        "mma.sync.aligned.m16n8k16.row.col.f32.bf16.bf16.f32 "
        "{%0,%1,%2,%3}, {%4,%5,%6,%7}, {%8,%9}, {%0,%1,%2,%3};"
        : "+f"(d[0]), "+f"(d[1]), "+f"(d[2]), "+f"(d[3])
        : "r"(a[0]), "r"(a[1]), "r"(a[2]), "r"(a[3]), "r"(b[0]), "r"(b[1]));
}
__device__ __forceinline__ void mma_f16(float* d, const uint32_t* a, const uint32_t* b) {
    asm volatile(
        "mma.sync.aligned.m16n8k16.row.col.f32.f16.f16.f32 "
        "{%0,%1,%2,%3}, {%4,%5,%6,%7}, {%8,%9}, {%0,%1,%2,%3};"
        : "+f"(d[0]), "+f"(d[1]), "+f"(d[2]), "+f"(d[3])
        : "r"(a[0]), "r"(a[1]), "r"(a[2]), "r"(a[3]), "r"(b[0]), "r"(b[1]));
}

// ============================================================================
// K0: CPB relative-position-bias table (one CTA)
// ============================================================================
__global__ void cpb_kernel(const float* __restrict__ rel_table,
                           const float* __restrict__ w1,
                           const float* __restrict__ b1,
                           const float* __restrict__ w2) {
    __shared__ float tab[225][16];
    const int t = threadIdx.x;
    if (t < 225) {
        float t0 = rel_table[t * 2 + 0];
        float t1 = rel_table[t * 2 + 1];
        float acc[16];
#pragma unroll
        for (int h = 0; h < 16; ++h) acc[h] = 0.f;
        for (int j = 0; j < 512; ++j) {
            float hv = fmaf(t0, w1[j], fmaf(t1, w1[512 + j], b1[j]));
            hv = fmaxf(hv, 0.f);
#pragma unroll
            for (int h = 0; h < 16; ++h) acc[h] = fmaf(hv, w2[j * 16 + h], acc[h]);
        }
#pragma unroll
        for (int h = 0; h < 16; ++h) tab[t][h] = acc[h];
    }
    __syncthreads();
    for (int e = t; e < 16 * 64 * 64; e += blockDim.x) {
        int h = e >> 12;
        int i = (e >> 6) & 63;
        int j = e & 63;
        int dh = (i >> 3) - (j >> 3) + 7;
        int dw = (i & 7) - (j & 7) + 7;
        float v = tab[dh * 15 + dw][h];
        g_bias[e] = 16.f / (1.f + expf(-v));
    }
}

// ============================================================================
// Conversion pre-passes
// ============================================================================
__global__ void convert_x(const float* __restrict__ src) {
    size_t i = (size_t)blockIdx.x * 256 + threadIdx.x;  // per float4
    float4 v = ((const float4*)src)[i];
    __nv_bfloat16 h0, h1, h2, h3, l0, l1, l2, l3;
    bsplit(v.x, h0, l0); bsplit(v.y, h1, l1);
    bsplit(v.z, h2, l2); bsplit(v.w, h3, l3);
    ((uint32_t*)g_xhi)[i * 2 + 0] = pack_bf(h0, h1);
    ((uint32_t*)g_xhi)[i * 2 + 1] = pack_bf(h2, h3);
    ((uint32_t*)g_xlo)[i * 2 + 0] = pack_bf(l0, l1);
    ((uint32_t*)g_xlo)[i * 2 + 1] = pack_bf(l2, l3);
    ((__half2*)g_xf16)[i * 2 + 0] = __floats2half2_rn(v.x, v.y);
    ((__half2*)g_xf16)[i * 2 + 1] = __floats2half2_rn(v.z, v.w);
}

// w_qkv is [512, 1536]; QK cols -> bf16 splits [n][k]; V cols -> fp16 [n-1024][k]
__global__ void convert_wqkv(const float* __restrict__ w) {
    int idx = blockIdx.x * 256 + threadIdx.x;
    if (idx >= 1536 * 512) return;
    int n = idx >> 9, k = idx & 511;
    float v = w[(size_t)k * 1536 + n];
    if (n < 1024) {
        __nv_bfloat16 h, l;
        bsplit(v, h, l);
        g_wqh[n * 512 + k] = h;
        g_wql[n * 512 + k] = l;
    } else {
        g_wv16[(n - 1024) * 512 + k] = __float2half_rn(v);
    }
}
__global__ void convert_proj(const float* __restrict__ w) {
    int idx = blockIdx.x * 256 + threadIdx.x;
    if (idx >= 512 * 512) return;
    int n = idx >> 9, k = idx & 511;
    g_wp16[idx] = __float2half_rn(w[(size_t)k * 512 + n]);
}

// ============================================================================
// Tensor-core GEMM via mma.sync. C[M,N] = A @ B^T, K=512, fp32 accum.
// (unchanged from round 16 — measured at the HMMA-issue roofline)
// ============================================================================
template <int MODE>
__global__ void __launch_bounds__(256) gemm_mma(const float* __restrict__ b1,
                                                float* __restrict__ outp) {
    constexpr int ST   = (MODE == 0) ? 40960 : 20480;
    constexpr int S    = (MODE == 0) ? 3 : 4;
    constexpr int BOFF = (MODE == 0) ? 20480 : 10240;

    extern __shared__ char smem[];
    const uint32_t sb = smem_u32(smem);
    const int tid = threadIdx.x, lane = tid & 31, wid = tid >> 5;
    const int m0 = blockIdx.y * 128, n0 = blockIdx.x * 128;
    const int wm = wid >> 2, wn = wid & 3;

    const uint16_t* __restrict__ Ahi =
        (MODE == 0) ? (const uint16_t*)g_xhi
                    : (MODE == 1) ? (const uint16_t*)g_xf16 : (const uint16_t*)g_of16;
    const uint16_t* __restrict__ Alo = (MODE == 0) ? (const uint16_t*)g_xlo : nullptr;
    const uint16_t* __restrict__ Bhi =
        (MODE == 0) ? (const uint16_t*)g_wqh
                    : (MODE == 1) ? (const uint16_t*)g_wv16 : (const uint16_t*)g_wp16;
    const uint16_t* __restrict__ Blo = (MODE == 0) ? (const uint16_t*)g_wql : nullptr;

    float acc[4][4][4];
#pragma unroll
    for (int i = 0; i < 4; ++i)
#pragma unroll
        for (int j = 0; j < 4; ++j)
#pragma unroll
            for (int f = 0; f < 4; ++f) acc[i][j][f] = 0.f;

    auto stage = [&](int ch, int buf) {
        const int k0 = ch * 32;
        const uint32_t s0 = sb + buf * ST;
#pragma unroll
        for (int it = 0; it < 2; ++it) {
            int idx = tid + it * 256;
            int r = idx >> 2;
            int kc = (idx & 3) * 8;
            uint32_t d = (uint32_t)(r * 80 + kc * 2);
            size_t ga = (size_t)(m0 + r) * 512 + k0 + kc;
            size_t gb = (size_t)(n0 + r) * 512 + k0 + kc;
            cp16(s0 + d, Ahi + ga);
            if (MODE == 0) {
                cp16(s0 + 10240 + d, Alo + ga);
                cp16(s0 + 20480 + d, Bhi + gb);
                cp16(s0 + 30720 + d, Blo + gb);
            } else {
                cp16(s0 + 10240 + d, Bhi + gb);
            }
        }
        cp_commit();
    };

    const uint32_t a_base = (uint32_t)((wm * 64 + (lane & 15)) * 80 + (lane >> 4) * 16);
    const uint32_t b_base = (uint32_t)((wn * 32 + (lane & 7) + ((lane >> 4) << 3)) * 80 +
                                       ((lane >> 3) & 1) * 16);

    stage(0, 0);
    stage(1, 1);
    if (S == 4) stage(2, 2);

    for (int ch = 0; ch < 16; ++ch) {
        const int rem = 15 - ch;
        if (S == 3) {
            if (rem >= 1) cp_wait1(); else cp_wait0();
        } else {
            if (rem >= 2) cp_wait2(); else if (rem == 1) cp_wait1(); else cp_wait0();
        }
        __syncthreads();
        if (ch + S - 1 < 16) stage(ch + S - 1, (ch + S - 1) % S);

        const uint32_t s0 = sb + (ch % S) * ST;
#pragma unroll
        for (int ks = 0; ks < 2; ++ks) {
            uint32_t ah[4][4], bh[4][2];
#pragma unroll
            for (int mt = 0; mt < 4; ++mt) {
                uint32_t addr = s0 + a_base + mt * 1280 + ks * 32;
                ldsm4(ah[mt][0], ah[mt][1], ah[mt][2], ah[mt][3], addr);
            }
#pragma unroll
            for (int p = 0; p < 2; ++p) {
                uint32_t addr = s0 + BOFF + b_base + p * 1280 + ks * 32;
                uint32_t r0, r1, r2, r3;
                ldsm4(r0, r1, r2, r3, addr);
                bh[2 * p][0] = r0; bh[2 * p][1] = r1;
                bh[2 * p + 1][0] = r2; bh[2 * p + 1][1] = r3;
            }
            if (MODE == 0) {
                uint32_t al[4][4], bl[4][2];
#pragma unroll
                for (int mt = 0; mt < 4; ++mt) {
                    uint32_t addr = s0 + 10240 + a_base + mt * 1280 + ks * 32;
                    ldsm4(al[mt][0], al[mt][1], al[mt][2], al[mt][3], addr);
                }
#pragma unroll
                for (int p = 0; p < 2; ++p) {
                    uint32_t addr = s0 + 30720 + b_base + p * 1280 + ks * 32;
                    uint32_t r0, r1, r2, r3;
                    ldsm4(r0, r1, r2, r3, addr);
                    bl[2 * p][0] = r0; bl[2 * p][1] = r1;
                    bl[2 * p + 1][0] = r2; bl[2 * p + 1][1] = r3;
                }
#pragma unroll
                for (int mt = 0; mt < 4; ++mt)
#pragma unroll
                    for (int nt = 0; nt < 4; ++nt)
                        mma_bf16(acc[mt][nt], ah[mt], bh[nt]);
#pragma unroll
                for (int mt = 0; mt < 4; ++mt)
#pragma unroll
                    for (int nt = 0; nt < 4; ++nt)
                        mma_bf16(acc[mt][nt], ah[mt], bl[nt]);
#pragma unroll
                for (int mt = 0; mt < 4; ++mt)
#pragma unroll
                    for (int nt = 0; nt < 4; ++nt)
                        mma_bf16(acc[mt][nt], al[mt], bh[nt]);
            } else {
#pragma unroll
                for (int mt = 0; mt < 4; ++mt)
#pragma unroll
                    for (int nt = 0; nt < 4; ++nt)
                        mma_f16(acc[mt][nt], ah[mt], bh[nt]);
            }
        }
        __syncthreads();
    }

#pragma unroll
    for (int mt = 0; mt < 4; ++mt) {
        int row = m0 + wm * 64 + mt * 16 + (lane >> 2);
#pragma unroll
        for (int nt = 0; nt < 4; ++nt) {
            int col = n0 + wn * 32 + nt * 8 + 2 * (lane & 3);
            if (MODE == 2) {
                float bv0 = b1[col], bv1 = b1[col + 1];
                float* dst = outp + (size_t)row * 512 + col;
                *(float2*)dst = make_float2(acc[mt][nt][0] + bv0, acc[mt][nt][1] + bv1);
                *(float2*)(dst + 8 * 512) =
                    make_float2(acc[mt][nt][2] + bv0, acc[mt][nt][3] + bv1);
            } else {
                int within, s;
                float* base;
                if (MODE == 0) {
                    s = col >> 9;
                    within = col & 511;
                    base = (s == 0) ? g_q : g_k;
                } else {
                    s = 2;
                    within = col;
                    base = g_v;
                }
                float bv0 = 0.f, bv1 = 0.f;
                if (MODE == 1) { bv0 = b1[within]; bv1 = b1[within + 1]; }
                else if (s == 0) { bv0 = b1[within]; bv1 = b1[within + 1]; }
                int hh = within >> 5, dd = within & 31;
                int b = row >> 6, n = row & 63;
                float* dst = base + (((size_t)b * 16 + hh) * 64 + n) * 32 + dd;
                *(float2*)dst = make_float2(acc[mt][nt][0] + bv0, acc[mt][nt][1] + bv1);
                *(float2*)(dst + 8 * 32) =
                    make_float2(acc[mt][nt][2] + bv0, acc[mt][nt][3] + bv1);
            }
        }
    }
}

// ============================================================================
// K2: fused attention per (window b, head h), TENSOR-CORE version. 128 thr.
// S = qn knT via bf16 hi/lo 3-pass MMA (logit precision), softmax on frags,
// P repacked fp32 C-frags -> fp16 A-frags (no smem trip), PV via fp16 MMA.
// smem: QH@0 QL@5120 KH@10240 KL@15360 (64 rows x 80B), VT@20480 (32 x 144B)
// ============================================================================
__global__ void __launch_bounds__(128) attn_kernel(
    const float* __restrict__ mask,
    const float* __restrict__ logit_scale)
{
    __shared__ char sm[20480 + 4608];
    const uint32_t sb = smem_u32(sm);
    const int t = threadIdx.x, lane = t & 31, w = t >> 5;
    const int h = blockIdx.x, b = blockIdx.y;
    const size_t base = ((size_t)b * 16 + h) * 2048;

    // ---- V -> transposed fp16 Vt[32][64] (stride 144B) ----
    {
        const float* vg = g_v + base;
#pragma unroll
        for (int i = 0; i < 16; ++i) {
            int idx = t + i * 128;
            int tok = idx >> 5, d = idx & 31;
            *(__half*)(sm + 20480 + d * 144 + tok * 2) = __float2half_rn(vg[idx]);
        }
    }

    // ---- normalize q (t<64) / k (t>=64), split bf16 hi/lo into smem ----
    {
        const float* src = (t < 64) ? (g_q + base + (size_t)t * 32)
                                    : (g_k + base + (size_t)(t - 64) * 32);
        float vals[32];
        float ss = 0.f;
#pragma unroll
        for (int i = 0; i < 8; ++i) {
            float4 v4 = *(const float4*)&src[i * 4];
            vals[i * 4 + 0] = v4.x; vals[i * 4 + 1] = v4.y;
            vals[i * 4 + 2] = v4.z; vals[i * 4 + 3] = v4.w;
            ss = fmaf(v4.x, v4.x, ss); ss = fmaf(v4.y, v4.y, ss);
            ss = fmaf(v4.z, v4.z, ss); ss = fmaf(v4.w, v4.w, ss);
        }
        float sc = rsqrtf(ss);
        if (t < 64) sc *= expf(fminf(logit_scale[h], LOG_SCALE_MAX));
        const uint32_t hoff = (t < 64) ? 0u : 10240u;
        const int row = t & 63;
        uint32_t hw[16], lw[16];
#pragma unroll
        for (int i = 0; i < 16; ++i) {
            float v0 = vals[2 * i] * sc, v1 = vals[2 * i + 1] * sc;
            __nv_bfloat16 h0, l0, h1, l1;
            bsplit(v0, h0, l0); bsplit(v1, h1, l1);
            hw[i] = pack_bf(h0, h1);
            lw[i] = pack_bf(l0, l1);
        }
#pragma unroll
        for (int i = 0; i < 4; ++i) {
            *(uint4*)(sm + hoff + row * 80 + i * 16) =
                make_uint4(hw[4 * i], hw[4 * i + 1], hw[4 * i + 2], hw[4 * i + 3]);
            *(uint4*)(sm + hoff + 5120 + row * 80 + i * 16) =
                make_uint4(lw[4 * i], lw[4 * i + 1], lw[4 * i + 2], lw[4 * i + 3]);
        }
    }
    __syncthreads();

    // ---- S = qn knT : warp w owns rows 16w..16w+15; 8 n-frags (64 cols) ----
    float S[8][4];
#pragma unroll
    for (int j = 0; j < 8; ++j)
#pragma unroll
        for (int f = 0; f < 4; ++f) S[j][f] = 0.f;

    const uint32_t a_addr = sb + (uint32_t)((w * 16 + (lane & 15)) * 80 + (lane >> 4) * 16);
    const uint32_t b_row  = (uint32_t)(((lane & 7) + ((lane >> 4) << 3)) * 80 +
                                       ((lane >> 3) & 1) * 16);
#pragma unroll
    for (int ks = 0; ks < 2; ++ks) {
        uint32_t aH[4], aL[4], bH[8][2], bL[8][2];
        ldsm4(aH[0], aH[1], aH[2], aH[3], a_addr + ks * 32);
        ldsm4(aL[0], aL[1], aL[2], aL[3], a_addr + 5120 + ks * 32);
#pragma unroll
        for (int p = 0; p < 4; ++p) {
            uint32_t r0, r1, r2, r3;
            ldsm4(r0, r1, r2, r3, sb + 10240 + b_row + p * 1280 + ks * 32);
            bH[2 * p][0] = r0; bH[2 * p][1] = r1;
            bH[2 * p + 1][0] = r2; bH[2 * p + 1][1] = r3;
            ldsm4(r0, r1, r2, r3, sb + 15360 + b_row + p * 1280 + ks * 32);
            bL[2 * p][0] = r0; bL[2 * p][1] = r1;
            bL[2 * p + 1][0] = r2; bL[2 * p + 1][1] = r3;
        }
#pragma unroll
        for (int j = 0; j < 8; ++j) mma_bf16(S[j], aH, bH[j]);
#pragma unroll
        for (int j = 0; j < 8; ++j) mma_bf16(S[j], aH, bL[j]);
#pragma unroll
        for (int j = 0; j < 8; ++j) mma_bf16(S[j], aL, bH[j]);
    }

    // ---- bias + mask + softmax on fragments ----
    const int row0 = w * 16 + (lane >> 2);   // rows row0, row0+8
    const int c0   = 2 * (lane & 3);
    const float* brow = g_bias + h * 4096;
    const float* mrow = mask + (size_t)(b & 255) * 4096;
    float m0 = -1e30f, m1 = -1e30f;
#pragma unroll
    for (int j = 0; j < 8; ++j) {
        int col = 8 * j + c0;
        float2 bb0 = *(const float2*)&brow[row0 * 64 + col];
        float2 mm0 = *(const float2*)&mrow[row0 * 64 + col];
        float2 bb1 = *(const float2*)&brow[(row0 + 8) * 64 + col];
        float2 mm1 = *(const float2*)&mrow[(row0 + 8) * 64 + col];
        S[j][0] += bb0.x + mm0.x; S[j][1] += bb0.y + mm0.y;
        S[j][2] += bb1.x + mm1.x; S[j][3] += bb1.y + mm1.y;
        m0 = fmaxf(m0, fmaxf(S[j][0], S[j][1]));
        m1 = fmaxf(m1, fmaxf(S[j][2], S[j][3]));
    }
    m0 = fmaxf(m0, __shfl_xor_sync(0xffffffffu, m0, 1));
    m0 = fmaxf(m0, __shfl_xor_sync(0xffffffffu, m0, 2));
    m1 = fmaxf(m1, __shfl_xor_sync(0xffffffffu, m1, 1));
    m1 = fmaxf(m1, __shfl_xor_sync(0xffffffffu, m1, 2));
    float s0 = 0.f, s1 = 0.f;
#pragma unroll
    for (int j = 0; j < 8; ++j) {
        S[j][0] = __expf(S[j][0] - m0); S[j][1] = __expf(S[j][1] - m0);
        S[j][2] = __expf(S[j][2] - m1); S[j][3] = __expf(S[j][3] - m1);
        s0 += S[j][0] + S[j][1];
        s1 += S[j][2] + S[j][3];
    }
    s0 += __shfl_xor_sync(0xffffffffu, s0, 1);
    s0 += __shfl_xor_sync(0xffffffffu, s0, 2);
    s1 += __shfl_xor_sync(0xffffffffu, s1, 1);
    s1 += __shfl_xor_sync(0xffffffffu, s1, 2);
    const float i0 = 1.f / s0, i1 = 1.f / s1;

    // ---- repack P (fp32 C-frags) -> fp16 A-frags, 1/sum folded ----
    uint32_t pa[4][4];
#pragma unroll
    for (int s = 0; s < 4; ++s) {
        pa[s][0] = pack_h2(S[2 * s][0] * i0, S[2 * s][1] * i0);
        pa[s][1] = pack_h2(S[2 * s][2] * i1, S[2 * s][3] * i1);
        pa[s][2] = pack_h2(S[2 * s + 1][0] * i0, S[2 * s + 1][1] * i0);
        pa[s][3] = pack_h2(S[2 * s + 1][2] * i1, S[2 * s + 1][3] * i1);
    }

    // ---- O = P V (fp16 MMA): n = 32 d-cols (4 frags), k = 64 tokens ----
    float O[4][4];
#pragma unroll
    for (int n = 0; n < 4; ++n)
#pragma unroll
        for (int f = 0; f < 4; ++f) O[n][f] = 0.f;
    const uint32_t v_row = (uint32_t)(((lane & 7) + ((lane >> 4) << 3)) * 144 +
                                      ((lane >> 3) & 1) * 16);
#pragma unroll
    for (int ks = 0; ks < 4; ++ks) {
        uint32_t vb[4][2];
#pragma unroll
        for (int p = 0; p < 2; ++p) {
            uint32_t r0, r1, r2, r3;
            ldsm4(r0, r1, r2, r3, sb + 20480 + v_row + p * 2304 + ks * 32);
            vb[2 * p][0] = r0; vb[2 * p][1] = r1;
            vb[2 * p + 1][0] = r2; vb[2 * p + 1][1] = r3;
        }
#pragma unroll
        for (int n = 0; n < 4; ++n) mma_f16(O[n], pa[ks], vb[n]);
    }

    // ---- store fp16 output [b*64+row][h*32+d] ----
#pragma unroll
    for (int n = 0; n < 4; ++n) {
        int d = 8 * n + c0;
        size_t o0 = ((size_t)b * 64 + row0) * 512 + h * 32 + d;
        *(uint32_t*)&g_of16[o0]            = pack_h2(O[n][0], O[n][1]);
        *(uint32_t*)&g_of16[o0 + 8 * 512]  = pack_h2(O[n][2], O[n][3]);
    }
}

// ============================================================================
// launch
// ============================================================================
extern "C" void kernel_launch(void* const* d_in, const int* in_sizes, int n_in,
                              void* d_out, int out_size) {
    const float* x           = (const float*)d_in[0];
    const float* mask        = (const float*)d_in[1];
    const float* rel_table   = (const float*)d_in[2];
    const float* w_qkv       = (const float*)d_in[3];
    const float* q_bias      = (const float*)d_in[4];
    const float* v_bias      = (const float*)d_in[5];
    const float* logit_scale = (const float*)d_in[6];
    const float* cpb_w1      = (const float*)d_in[7];
    const float* cpb_b1      = (const float*)d_in[8];
    const float* cpb_w2      = (const float*)d_in[9];
    const float* proj_w      = (const float*)d_in[10];
    const float* proj_b      = (const float*)d_in[11];
    float* out = (float*)d_out;

    const int SMEM0 = 3 * 40960;   // 122880
    const int SMEM1 = 4 * 20480;   // 81920
    cudaFuncSetAttribute(gemm_mma<0>, cudaFuncAttributeMaxDynamicSharedMemorySize, SMEM0);
    cudaFuncSetAttribute(gemm_mma<1>, cudaFuncAttributeMaxDynamicSharedMemorySize, SMEM1);
    cudaFuncSetAttribute(gemm_mma<2>, cudaFuncAttributeMaxDynamicSharedMemorySize, SMEM1);

    // tiny pre-passes
    cpb_kernel<<<1, 256>>>(rel_table, cpb_w1, cpb_b1, cpb_w2);
    convert_x<<<65536, 256>>>(x);
    convert_wqkv<<<3072, 256>>>(w_qkv);
    convert_proj<<<1024, 256>>>(proj_w);

    // K1a: Q,K columns (bf16 3-pass split) -> g_q/g_k
    gemm_mma<0><<<dim3(8, 1024), 256, SMEM0>>>(q_bias, nullptr);
    // K1b: V columns (fp16 1-pass) -> g_v
    gemm_mma<1><<<dim3(4, 1024), 256, SMEM1>>>(v_bias, nullptr);

    // K2: fused window attention (tensor cores) -> g_of16
    attn_kernel<<<dim3(16, 2048), 128>>>(mask, logit_scale);

    // K3: output projection (fp16 1-pass) -> out
    gemm_mma<2><<<dim3(4, 1024), 256, SMEM1>>>(proj_b, out);
}